// round 14
// baseline (speedup 1.0000x reference)
#include <cuda_runtime.h>

__device__ double g_acc = 0.0;
__device__ unsigned int g_done = 0;

#define THREADS 256
#define TILE_ROWS 512
#define F4_DATA (TILE_ROWS * 5 / 4)      // 640 float4 = 10KB per tile
#define NBUF 3

__device__ __forceinline__ void cp16(void* smem_dst, const void* gmem_src) {
    unsigned int s = (unsigned int)__cvta_generic_to_shared(smem_dst);
    asm volatile("cp.async.cg.shared.global [%0], [%1], 16;"
                 :: "r"(s), "l"(gmem_src) : "memory");
}
__device__ __forceinline__ unsigned long long f2ll(float a, float b) {
    unsigned long long r;
    asm("mov.b64 %0, {%1, %2};" : "=l"(r) : "f"(a), "f"(b));
    return r;
}
__device__ __forceinline__ unsigned long long add2(unsigned long long a,
                                                   unsigned long long b) {
    unsigned long long r;
    asm("add.rn.f32x2 %0, %1, %2;" : "=l"(r) : "l"(a), "l"(b));
    return r;
}
__device__ __forceinline__ unsigned long long mul2(unsigned long long a,
                                                   unsigned long long b) {
    unsigned long long r;
    asm("mul.rn.f32x2 %0, %1, %2;" : "=l"(r) : "l"(a), "l"(b));
    return r;
}
__device__ __forceinline__ void unpack2(unsigned long long v, float& lo, float& hi) {
    asm("mov.b64 {%0, %1}, %2;" : "=f"(lo), "=f"(hi) : "l"(v));
}
__device__ __forceinline__ float ex2f(float x) {
    float r;
    asm("ex2.approx.f32 %0, %1;" : "=f"(r) : "f"(x));
    return r;
}

__global__ void __launch_bounds__(THREADS, 7)
bloom_loss_kernel(const float* __restrict__ inputs,
                  const int* __restrict__ targets,
                  float* __restrict__ out,
                  int B, int numTiles, double invB)
{
    __shared__ float sdata[NBUF][TILE_ROWS * 5];       // 3 x 10KB
    __shared__ float Tt[5 * 12];                       // padded T rows, stride 48B
    __shared__ float warp_sums[THREADS / 32];

    const int tid = threadIdx.x;
    const int lane = tid & 31;
    const int wid = tid >> 5;

    // T table: row stride 12 floats -> LDS.128 at t*48B touches disjoint banks
    if (tid < 60) {
        int t = tid / 12, j = tid % 12;
        int d = t - j; d = d < 0 ? -d : d;
        Tt[tid] = (j < 5) ? ((d >= 3) ? 2.0f : 0.5f * (float)d) : 0.0f;
    }

    const float4* __restrict__ in4 = (const float4*)inputs;
    const int grid = gridDim.x;
    const int t0 = blockIdx.x;

    // stage tile data (always commits a group so wait_group counting is uniform)
    auto stage = [&](int tileIdx, int buf) {
        if (tileIdx < numTiles) {
            int tileRow = tileIdx * TILE_ROWS;
            if (tileRow + TILE_ROWS <= B) {
                int baseF4 = tileIdx * F4_DATA;
                #pragma unroll
                for (int q = 0; q < 3; q++) {
                    int idx = q * THREADS + tid;
                    if (idx < F4_DATA)
                        cp16(&((float4*)sdata[buf])[idx], &in4[baseF4 + idx]);
                }
            } else {
                for (int r = tid; r < TILE_ROWS; r += THREADS) {
                    int row = tileRow + r;
                    #pragma unroll
                    for (int j = 0; j < 5; j++)
                        sdata[buf][r * 5 + j] = (row < B) ? inputs[row * 5 + j] : 0.0f;
                }
            }
        }
        asm volatile("cp.async.commit_group;" ::: "memory");
    };
    auto load_tg = [&](int tileIdx) -> int2 {
        int2 r = make_int2(0, 0);
        int tileRow = tileIdx * TILE_ROWS;
        if (tileRow + TILE_ROWS <= B) {
            r = ((const int2*)targets)[(tileRow >> 1) + tid];
        } else {
            int row = tileRow + 2 * tid;
            if (row < B) r.x = targets[row];
            if (row + 1 < B) r.y = targets[row + 1];
        }
        return r;
    };

    float localA = 0.0f;
    unsigned long long sum2 = 0;   // packed f32x2 sum of all x (linear CE term)

    const float LOG2E = 1.4426950408889634f;
    const unsigned long long C2 = f2ll(LOG2E, LOG2E);

    stage(t0, 0);
    stage(t0 + grid, 1);
    int2 tg_cur = load_tg(t0);

    int bufc = 0, bufs = 2;
    for (int t = t0; t < numTiles; t += grid) {
        stage(t + 2 * grid, bufs);
        int tn = t + grid;
        int2 tg_next = (tn < numTiles) ? load_tg(tn) : make_int2(0, 0);

        // committed so far includes 2 tiles ahead; allow 2 outstanding -> tile t done
        asm volatile("cp.async.wait_group 2;" ::: "memory");
        __syncthreads();

        const int tileRow = t * TILE_ROWS;
        const bool fullTile = (tileRow + TILE_ROWS) <= B;

        // 2 rows/thread: 10 contiguous floats -> 5 conflict-free LDS.64
        const float2* sr = (const float2*)sdata[bufc] + tid * 5;
        float2 p0 = sr[0], p1 = sr[1], p2 = sr[2], p3 = sr[3], p4 = sr[4];

        if (fullTile) {
            unsigned long long l0 = f2ll(p0.x, p0.y), l1 = f2ll(p1.x, p1.y);
            unsigned long long l2 = f2ll(p2.x, p2.y), l3 = f2ll(p3.x, p3.y);
            unsigned long long l4 = f2ll(p4.x, p4.y);
            // linear term accumulation (packed)
            sum2 = add2(sum2, add2(add2(add2(l0, l1), add2(l2, l3)), l4));
            // packed premultiply by log2(e), then scalar ex2
            float y0, y1, y2, y3, y4, y5, y6, y7, y8, y9;
            unpack2(mul2(l0, C2), y0, y1);
            unpack2(mul2(l1, C2), y2, y3);
            unpack2(mul2(l2, C2), y4, y5);
            unpack2(mul2(l3, C2), y6, y7);
            unpack2(mul2(l4, C2), y8, y9);
            float e0 = ex2f(y0), e1 = ex2f(y1), e2 = ex2f(y2), e3 = ex2f(y3);
            float e4 = ex2f(y4), e5 = ex2f(y5), e6 = ex2f(y6), e7 = ex2f(y7);
            float e8 = ex2f(y8), e9 = ex2f(y9);

            // row 0
            {
                int tt = tg_cur.x;
                const float4 wv = *(const float4*)(Tt + tt * 12);
                const float w4 = Tt[tt * 12 + 4];
                float xt = sdata[bufc][(2 * tid) * 5 + tt];
                float s = ((e0 + e1) + (e2 + e3)) + e4;
                float pen = fmaf(e4, w4, fmaf(e3, wv.w,
                            fmaf(e2, wv.z, fmaf(e1, wv.y, e0 * wv.x))));
                localA += (__logf(s) - 0.875f * xt) + 0.1f * __fdividef(pen, s);
            }
            // row 1
            {
                int tt = tg_cur.y;
                const float4 wv = *(const float4*)(Tt + tt * 12);
                const float w4 = Tt[tt * 12 + 4];
                float xt = sdata[bufc][(2 * tid + 1) * 5 + tt];
                float s = ((e5 + e6) + (e7 + e8)) + e9;
                float pen = fmaf(e9, w4, fmaf(e8, wv.w,
                            fmaf(e7, wv.z, fmaf(e6, wv.y, e5 * wv.x))));
                localA += (__logf(s) - 0.875f * xt) + 0.1f * __fdividef(pen, s);
            }
        } else {
            // rare partial tail tile: fully guarded scalar path
            float x[10] = {p0.x, p0.y, p1.x, p1.y, p2.x,
                           p2.y, p3.x, p3.y, p4.x, p4.y};
            int tgt2[2] = {tg_cur.x, tg_cur.y};
            #pragma unroll
            for (int r = 0; r < 2; r++) {
                int row = tileRow + 2 * tid + r;
                if (row < B) {
                    int tt = tgt2[r];
                    float sx_ = 0.0f, s = 0.0f, pen = 0.0f, xt = 0.0f;
                    #pragma unroll
                    for (int j = 0; j < 5; j++) {
                        float xv = x[r * 5 + j];
                        float e = __expf(xv);
                        s += e; sx_ += xv;
                        int d = tt - j; d = d < 0 ? -d : d;
                        float w = (d >= 3) ? 2.0f : 0.5f * (float)d;
                        pen = fmaf(e, w, pen);
                        xt = (j == tt) ? xv : xt;
                    }
                    localA += (__logf(s) - 0.875f * xt) + 0.1f * __fdividef(pen, s);
                    sum2 = add2(sum2, f2ll(sx_, 0.0f));
                }
            }
        }
        tg_cur = tg_next;
        __syncthreads();   // reads of bufc done before it can be restaged

        bufc = (bufc == NBUF - 1) ? 0 : bufc + 1;
        bufs = (bufs == NBUF - 1) ? 0 : bufs + 1;
    }

    // fold linear term: local = localA - 0.025 * (sum2.lo + sum2.hi)
    float slo, shi;
    unpack2(sum2, slo, shi);
    float local = fmaf(-0.025f, slo + shi, localA);

    #pragma unroll
    for (int off = 16; off > 0; off >>= 1)
        local += __shfl_xor_sync(0xFFFFFFFFu, local, off);
    if (lane == 0) warp_sums[wid] = local;
    __syncthreads();

    if (tid == 0) {
        float bs = 0.0f;
        #pragma unroll
        for (int i = 0; i < THREADS / 32; i++) bs += warp_sums[i];
        atomicAdd(&g_acc, (double)bs);
        __threadfence();
        unsigned int old = atomicAdd(&g_done, 1u);
        if (old == gridDim.x - 1) {
            double v = atomicAdd(&g_acc, 0.0);
            out[0] = (float)(v * invB);
            g_acc = 0.0;
            g_done = 0u;
        }
    }
}

extern "C" void kernel_launch(void* const* d_in, const int* in_sizes, int n_in,
                              void* d_out, int out_size) {
    const float* inputs = (const float*)d_in[0];
    const int* targets = (const int*)d_in[1];
    float* out = (float*)d_out;

    int B = in_sizes[1];
    int numTiles = (B + TILE_ROWS - 1) / TILE_ROWS;
    int blocks = 148 * 7;
    if (blocks > numTiles) blocks = numTiles;
    if (blocks < 1) blocks = 1;

    bloom_loss_kernel<<<blocks, THREADS>>>(inputs, targets, out, B, numTiles,
                                           1.0 / (double)B);
}

// round 15
// speedup vs baseline: 1.1356x; 1.1356x over previous
#include <cuda_runtime.h>

__device__ double g_acc = 0.0;
__device__ unsigned int g_done = 0;

#define THREADS 256
#define TILE_ROWS 1024
#define F4_DATA (TILE_ROWS * 5 / 4)      // 1280 float4 = 20KB per tile
#define NBUF 2

__device__ __forceinline__ void cp16(void* smem_dst, const void* gmem_src) {
    unsigned int s = (unsigned int)__cvta_generic_to_shared(smem_dst);
    asm volatile("cp.async.cg.shared.global [%0], [%1], 16;"
                 :: "r"(s), "l"(gmem_src) : "memory");
}
__device__ __forceinline__ unsigned long long f2ll(float a, float b) {
    unsigned long long r;
    asm("mov.b64 %0, {%1, %2};" : "=l"(r) : "f"(a), "f"(b));
    return r;
}
__device__ __forceinline__ unsigned long long add2(unsigned long long a,
                                                   unsigned long long b) {
    unsigned long long r;
    asm("add.rn.f32x2 %0, %1, %2;" : "=l"(r) : "l"(a), "l"(b));
    return r;
}
__device__ __forceinline__ void unpack2(unsigned long long v, float& lo, float& hi) {
    asm("mov.b64 {%0, %1}, %2;" : "=f"(lo), "=f"(hi) : "l"(v));
}
__device__ __forceinline__ float lg2f(float x) {
    float r;
    asm("lg2.approx.f32 %0, %1;" : "=f"(r) : "f"(x));
    return r;
}
__device__ __forceinline__ float rcpf(float x) {
    float r;
    asm("rcp.approx.f32 %0, %1;" : "=f"(r) : "f"(x));
    return r;
}

__global__ void __launch_bounds__(THREADS, 4)
bloom_loss_kernel(const float* __restrict__ inputs,
                  const int* __restrict__ targets,
                  float* __restrict__ out,
                  int B, int numTiles, double invB)
{
    __shared__ float sdata[NBUF][TILE_ROWS * 5];       // 2 x 20KB
    __shared__ float Tt[5 * 12];                       // padded T rows, stride 48B
    __shared__ float warp_sums[THREADS / 32];

    const int tid = threadIdx.x;
    const int lane = tid & 31;
    const int wid = tid >> 5;

    // T table: row stride 12 floats -> LDS.128 at t*48B touches disjoint banks
    if (tid < 60) {
        int t = tid / 12, j = tid % 12;
        int d = t - j; d = d < 0 ? -d : d;
        Tt[tid] = (j < 5) ? ((d >= 3) ? 2.0f : 0.5f * (float)d) : 0.0f;
    }

    const float4* __restrict__ in4 = (const float4*)inputs;
    const int grid = gridDim.x;
    const int t0 = blockIdx.x;

    auto stage = [&](int tileIdx, int buf) {
        if (tileIdx < numTiles) {
            int tileRow = tileIdx * TILE_ROWS;
            if (tileRow + TILE_ROWS <= B) {
                int baseF4 = tileIdx * F4_DATA;
                #pragma unroll
                for (int q = 0; q < 5; q++) {           // 5*256 = 1280 exactly
                    int idx = q * THREADS + tid;
                    cp16(&((float4*)sdata[buf])[idx], &in4[baseF4 + idx]);
                }
            } else {
                for (int r = tid; r < TILE_ROWS; r += THREADS) {
                    int row = tileRow + r;
                    #pragma unroll
                    for (int j = 0; j < 5; j++)
                        sdata[buf][r * 5 + j] = (row < B) ? inputs[row * 5 + j] : 0.0f;
                }
            }
        }
        asm volatile("cp.async.commit_group;" ::: "memory");
    };
    auto load_tg = [&](int tileIdx) -> int4 {
        int4 r = make_int4(0, 0, 0, 0);
        if (tileIdx < numTiles) {
            int tileRow = tileIdx * TILE_ROWS;
            if (tileRow + TILE_ROWS <= B) {
                r = ((const int4*)targets)[(tileRow >> 2) + tid];
            } else {
                int row = tileRow + 4 * tid;
                int* rp = (int*)&r;
                #pragma unroll
                for (int q = 0; q < 4; q++)
                    if (row + q < B) rp[q] = targets[row + q];
            }
        }
        return r;
    };

    float localLg = 0.0f;     // sum of log2(s)           (x ln2 at end)
    float localR = 0.0f;      // -0.875*xt + 0.1*pen/s terms
    unsigned long long sum2 = 0;  // packed f32x2 sum of all x (linear CE term)

    int4 tg_cur = load_tg(t0);
    stage(t0, 0);

    int k = 0;
    for (int t = t0; t < numTiles; t += grid, k++) {
        stage(t + grid, (k + 1) & 1);
        asm volatile("cp.async.wait_group 1;" ::: "memory");
        __syncthreads();

        int4 tg_next = load_tg(t + grid);   // overlaps entire compute phase

        const int buf = k & 1;
        const int tileRow = t * TILE_ROWS;
        const bool fullTile = (tileRow + TILE_ROWS) <= B;

        // 4 rows/thread: 20 contiguous floats -> 5 conflict-free LDS.128
        const float4* sr = (const float4*)sdata[buf] + tid * 5;
        float4 v0 = sr[0], v1 = sr[1], v2 = sr[2], v3 = sr[3], v4 = sr[4];
        float x[20] = {v0.x, v0.y, v0.z, v0.w,
                       v1.x, v1.y, v1.z, v1.w,
                       v2.x, v2.y, v2.z, v2.w,
                       v3.x, v3.y, v3.z, v3.w,
                       v4.x, v4.y, v4.z, v4.w};
        int tgt4[4] = {tg_cur.x, tg_cur.y, tg_cur.z, tg_cur.w};

        if (fullTile) {
            // packed accumulation of the global linear term (0.025 * sum x)
            unsigned long long a = add2(f2ll(v0.x, v0.y), f2ll(v0.z, v0.w));
            unsigned long long b = add2(f2ll(v1.x, v1.y), f2ll(v1.z, v1.w));
            unsigned long long c = add2(f2ll(v2.x, v2.y), f2ll(v2.z, v2.w));
            unsigned long long d = add2(f2ll(v3.x, v3.y), f2ll(v3.z, v3.w));
            unsigned long long e2_ = add2(f2ll(v4.x, v4.y), f2ll(v4.z, v4.w));
            sum2 = add2(sum2, add2(add2(add2(a, b), add2(c, d)), e2_));

            #pragma unroll
            for (int r = 0; r < 4; r++) {
                int tt = tgt4[r];
                const float4 wv = *(const float4*)(Tt + tt * 12);
                const float w4 = Tt[tt * 12 + 4];
                float xt = sdata[buf][(4 * tid + r) * 5 + tt];   // 1 dynamic LDS

                float e0 = __expf(x[r * 5 + 0]);
                float e1 = __expf(x[r * 5 + 1]);
                float e2 = __expf(x[r * 5 + 2]);
                float e3 = __expf(x[r * 5 + 3]);
                float e4 = __expf(x[r * 5 + 4]);
                float s = ((e0 + e1) + (e2 + e3)) + e4;
                float pen = fmaf(e4, w4, fmaf(e3, wv.w,
                            fmaf(e2, wv.z, fmaf(e1, wv.y, e0 * wv.x))));
                localLg += lg2f(s);
                localR += fmaf(0.1f * pen, rcpf(s), -0.875f * xt);
            }
        } else {
            // rare partial tail tile: fully guarded scalar path
            #pragma unroll
            for (int r = 0; r < 4; r++) {
                int row = tileRow + 4 * tid + r;
                if (row < B) {
                    int tt = tgt4[r];
                    float sx_ = 0.0f, s = 0.0f, pen = 0.0f, xt = 0.0f;
                    #pragma unroll
                    for (int j = 0; j < 5; j++) {
                        float xv = x[r * 5 + j];
                        float e = __expf(xv);
                        s += e; sx_ += xv;
                        int d = tt - j; d = d < 0 ? -d : d;
                        float w = (d >= 3) ? 2.0f : 0.5f * (float)d;
                        pen = fmaf(e, w, pen);
                        xt = (j == tt) ? xv : xt;
                    }
                    localLg += lg2f(s);
                    localR += fmaf(0.1f * pen, rcpf(s), -0.875f * xt);
                    sum2 = add2(sum2, f2ll(sx_, 0.0f));
                }
            }
        }
        tg_cur = tg_next;
        __syncthreads();   // reads of buf done before it can be restaged
    }

    // local = ln2 * localLg + localR - 0.025 * (sum2.lo + sum2.hi)
    float slo, shi;
    unpack2(sum2, slo, shi);
    float local = fmaf(0.6931471805599453f, localLg,
                  fmaf(-0.025f, slo + shi, localR));

    #pragma unroll
    for (int off = 16; off > 0; off >>= 1)
        local += __shfl_xor_sync(0xFFFFFFFFu, local, off);
    if (lane == 0) warp_sums[wid] = local;
    __syncthreads();

    if (tid == 0) {
        float bs = 0.0f;
        #pragma unroll
        for (int i = 0; i < THREADS / 32; i++) bs += warp_sums[i];
        atomicAdd(&g_acc, (double)bs);
        __threadfence();
        unsigned int old = atomicAdd(&g_done, 1u);
        if (old == gridDim.x - 1) {
            double v = atomicAdd(&g_acc, 0.0);
            out[0] = (float)(v * invB);
            g_acc = 0.0;
            g_done = 0u;
        }
    }
}

extern "C" void kernel_launch(void* const* d_in, const int* in_sizes, int n_in,
                              void* d_out, int out_size) {
    const float* inputs = (const float*)d_in[0];
    const int* targets = (const int*)d_in[1];
    float* out = (float*)d_out;

    int B = in_sizes[1];
    int numTiles = (B + TILE_ROWS - 1) / TILE_ROWS;
    int blocks = 148 * 4;
    if (blocks > numTiles) blocks = numTiles;
    if (blocks < 1) blocks = 1;

    bloom_loss_kernel<<<blocks, THREADS>>>(inputs, targets, out, B, numTiles,
                                           1.0 / (double)B);
}